// round 1
// baseline (speedup 1.0000x reference)
#include <cuda_runtime.h>
#include <math.h>

#define BB 32
#define NN 2048
#define MM 2048
#define TPB 128
#define BPB (NN / TPB)   // 16 blocks per batch
#define LOG2E 1.4426950408889634f

// Scratch (no allocations allowed in kernel_launch)
__device__ float4 g_coef[BB * MM];        // (tx, ty, -log2e*|t|^2, 0) per target point
__device__ float  g_T[BB * 4];            // rigid transform per batch: c, s, tx, ty
__device__ float  g_part[BB * BPB * 8];   // per-block partial sums

__device__ __forceinline__ float ex2(float x) {
    float y;
    asm("ex2.approx.ftz.f32 %0, %1;" : "=f"(y) : "f"(x));
    return y;
}

// ---------------------------------------------------------------------------
// Prep: init T from init_transformation; precompute target coefficients.
// ---------------------------------------------------------------------------
__global__ void prep_kernel(const float* __restrict__ target,
                            const float* __restrict__ init) {
    int idx = blockIdx.x * blockDim.x + threadIdx.x;
    if (idx < BB) {
        float th = init[idx * 3 + 0];
        g_T[idx * 4 + 0] = cosf(th);
        g_T[idx * 4 + 1] = sinf(th);
        g_T[idx * 4 + 2] = init[idx * 3 + 1];
        g_T[idx * 4 + 3] = init[idx * 3 + 2];
    }
    if (idx < BB * MM) {
        float tx = target[idx * 2 + 0];
        float ty = target[idx * 2 + 1];
        g_coef[idx] = make_float4(tx, ty, -LOG2E * (tx * tx + ty * ty), 0.f);
    }
}

// ---------------------------------------------------------------------------
// Main fused iteration: per row -> softmax correspondence -> block partials.
// grid = (BPB, BB), block = TPB. Each thread owns one source row.
// ---------------------------------------------------------------------------
__global__ __launch_bounds__(TPB) void iter_kernel(const float* __restrict__ source) {
    __shared__ float4 sm[MM];       // 32 KB target coefficient tile
    __shared__ float  red[4][8];

    const int b   = blockIdx.y;
    const int tid = threadIdx.x;
    const int row = blockIdx.x * TPB + tid;

    const float4* cf = g_coef + b * MM;
#pragma unroll
    for (int i = 0; i < MM / TPB; i++) sm[tid + i * TPB] = cf[tid + i * TPB];

    const float Tc  = g_T[b * 4 + 0];
    const float Tsn = g_T[b * 4 + 1];
    const float Ttx = g_T[b * 4 + 2];
    const float Tty = g_T[b * 4 + 3];

    const float sx = source[(b * NN + row) * 2 + 0];
    const float sy = source[(b * NN + row) * 2 + 1];
    const float stx = Tc * sx - Tsn * sy + Ttx;
    const float sty = Tsn * sx + Tc * sy + Tty;

    __syncthreads();

    const float px = 2.f * LOG2E * stx;
    const float py = 2.f * LOG2E * sty;
    // exact upper bound on logit (log2 domain): logit - bnd = -log2e*|st - t|^2 <= 0
    const float nb = -LOG2E * (stx * stx + sty * sty);

    float s0 = 0.f, s1 = 0.f, s2 = 0.f, s3 = 0.f;
    float ax0 = 0.f, ax1 = 0.f, ax2 = 0.f, ax3 = 0.f;
    float ay0 = 0.f, ay1 = 0.f, ay2 = 0.f, ay3 = 0.f;

#pragma unroll 2
    for (int m = 0; m < MM; m += 4) {
        float4 t0 = sm[m + 0];
        float4 t1 = sm[m + 1];
        float4 t2 = sm[m + 2];
        float4 t3 = sm[m + 3];
        float e0 = ex2(fmaf(py, t0.y, t0.z) + fmaf(px, t0.x, nb));
        float e1 = ex2(fmaf(py, t1.y, t1.z) + fmaf(px, t1.x, nb));
        float e2 = ex2(fmaf(py, t2.y, t2.z) + fmaf(px, t2.x, nb));
        float e3 = ex2(fmaf(py, t3.y, t3.z) + fmaf(px, t3.x, nb));
        s0 += e0; ax0 = fmaf(e0, t0.x, ax0); ay0 = fmaf(e0, t0.y, ay0);
        s1 += e1; ax1 = fmaf(e1, t1.x, ax1); ay1 = fmaf(e1, t1.y, ay1);
        s2 += e2; ax2 = fmaf(e2, t2.x, ax2); ay2 = fmaf(e2, t2.y, ay2);
        s3 += e3; ax3 = fmaf(e3, t3.x, ax3); ay3 = fmaf(e3, t3.y, ay3);
    }

    const float sum = (s0 + s1) + (s2 + s3);
    const float ax  = (ax0 + ax1) + (ax2 + ax3);
    const float ay  = (ay0 + ay1) + (ay2 + ay3);
    const float inv = 1.0f / sum;
    const float tcx = ax * inv;
    const float tcy = ay * inv;

    // 8 per-batch reduction terms: sums of st, tc, and st (x) tc outer products
    float v[8];
    v[0] = stx;        v[1] = sty;
    v[2] = tcx;        v[3] = tcy;
    v[4] = stx * tcx;  v[5] = stx * tcy;
    v[6] = sty * tcx;  v[7] = sty * tcy;

#pragma unroll
    for (int off = 16; off > 0; off >>= 1) {
#pragma unroll
        for (int k = 0; k < 8; k++)
            v[k] += __shfl_down_sync(0xffffffffu, v[k], off);
    }
    const int wid = tid >> 5;
    const int lane = tid & 31;
    if (lane == 0) {
#pragma unroll
        for (int k = 0; k < 8; k++) red[wid][k] = v[k];
    }
    __syncthreads();
    if (tid < 8) {
        float r = (red[0][tid] + red[1][tid]) + (red[2][tid] + red[3][tid]);
        g_part[(b * BPB + blockIdx.x) * 8 + tid] = r;
    }
}

// ---------------------------------------------------------------------------
// Update: combine partials (fixed order, double), Kabsch via polar factor of
// H^T (== V U^T of the SVD, including the det<0 reflection case), compose T.
// ---------------------------------------------------------------------------
__global__ void update_kernel(float* __restrict__ out, int write_out) {
    int b = threadIdx.x;
    if (b >= BB) return;

    double S[8];
#pragma unroll
    for (int k = 0; k < 8; k++) S[k] = 0.0;
    for (int blk = 0; blk < BPB; blk++)
#pragma unroll
        for (int k = 0; k < 8; k++)
            S[k] += (double)g_part[(b * BPB + blk) * 8 + k];

    const double n = (double)NN;
    const double csx = S[0] / n, csy = S[1] / n;
    const double ctx = S[2] / n, cty = S[3] / n;

    // H[d][e] = sum st_d tc_e  - n * cs_d * ct_e
    const double H00 = S[4] - S[0] * S[2] / n;
    const double H01 = S[5] - S[0] * S[3] / n;
    const double H10 = S[6] - S[1] * S[2] / n;
    const double H11 = S[7] - S[1] * S[3] / n;

    // Polar factor of A = H^T:  A = B(rot) + C(refl); pick larger part.
    const double b0 = H00 + H11;       // rotation part
    const double b1 = H10 - H01;
    const double c0 = H00 - H11;       // reflection part
    const double c1 = H10 + H01;

    double R00, R01, R10, R11;
    if (b0 * b0 + b1 * b1 >= c0 * c0 + c1 * c1) {
        double h = sqrt(b0 * b0 + b1 * b1);
        double ih = (h > 0.0) ? 1.0 / h : 0.0;
        R00 = b0 * ih;  R01 = b1 * ih;
        R10 = -b1 * ih; R11 = b0 * ih;
    } else {
        double h = sqrt(c0 * c0 + c1 * c1);
        double ih = (h > 0.0) ? 1.0 / h : 0.0;
        R00 = c0 * ih;  R01 = c1 * ih;
        R10 = c1 * ih;  R11 = -c0 * ih;
    }

    const double tdx = ctx - (R00 * csx + R01 * csy);
    const double tdy = cty - (R10 * csx + R11 * csy);

    // delta rotation actually applied = R(atan2(R10, R00)) (matches reference's
    // vec2mat(delta_theta)), reconstructed without trig:
    double nn = sqrt(R00 * R00 + R10 * R10);
    double inh = (nn > 0.0) ? 1.0 / nn : 0.0;
    const double cd = R00 * inh;
    const double sd = R10 * inh;

    const float Tc  = g_T[b * 4 + 0];
    const float Tsn = g_T[b * 4 + 1];
    const float Ttx = g_T[b * 4 + 2];
    const float Tty = g_T[b * 4 + 3];

    const float nc  = (float)(cd * (double)Tc - sd * (double)Tsn);
    const float ns  = (float)(sd * (double)Tc + cd * (double)Tsn);
    const float ntx = (float)(cd * (double)Ttx - sd * (double)Tty + tdx);
    const float nty = (float)(sd * (double)Ttx + cd * (double)Tty + tdy);

    g_T[b * 4 + 0] = nc;
    g_T[b * 4 + 1] = ns;
    g_T[b * 4 + 2] = ntx;
    g_T[b * 4 + 3] = nty;

    if (write_out) {
        out[b * 3 + 0] = atan2f(ns, nc);
        out[b * 3 + 1] = ntx;
        out[b * 3 + 2] = nty;
    }
}

// ---------------------------------------------------------------------------
extern "C" void kernel_launch(void* const* d_in, const int* in_sizes, int n_in,
                              void* d_out, int out_size) {
    const float* source = (const float*)d_in[0];
    const float* target = (const float*)d_in[1];
    const float* init   = (const float*)d_in[2];
    float* out = (float*)d_out;

    prep_kernel<<<(BB * MM + 255) / 256, 256>>>(target, init);
    for (int it = 0; it < 5; it++) {
        iter_kernel<<<dim3(BPB, BB), TPB>>>(source);
        update_kernel<<<1, 32>>>(out, (it == 4) ? 1 : 0);
    }
}